// round 4
// baseline (speedup 1.0000x reference)
#include <cuda_runtime.h>
#include <cuda_bf16.h>

// MaskFiller: out[b, keep_ids[b,k], :] = inputs[b,k,:]
//             out[b, mask_ids[b,m], :] = mask_embedding[:]
// B=8, K=4096, M=4096, L=8192, D=512 (f32). Pure scatter-copy; HBM bound.
//
// Inputs (metadata order):
//   d_in[0] inputs            float32 [B, K, D]
//   d_in[1] mask_position_ids int32   [B, M]
//   d_in[2] keep_position_ids int32   [B, K]
//   d_in[3] mask_embedding    float32 [D]
//   d_in[4] axis              (scalar, unused; always -2)

#define B_ 8
#define K_ 4096
#define M_ 4096
#define L_ (K_ + M_)
#define D_ 512
#define VEC_PER_ROW (D_ / 4)   // 128 float4 per row

__global__ __launch_bounds__(128, 16)
void maskfiller_kernel(const float4* __restrict__ inputs,
                       const int*    __restrict__ mask_ids,
                       const int*    __restrict__ keep_ids,
                       const float4* __restrict__ mask_emb,
                       float4*       __restrict__ out)
{
    // One CTA per output task. Task t covers batch b, slot j within [0, L).
    // j < K  -> copy inputs row k=j to out row keep_ids[b*K + j]
    // j >= K -> write mask_emb to out row mask_ids[b*M + (j-K)]
    const int t   = blockIdx.x;          // 0 .. B*L-1
    const int b   = t >> 13;             // t / L_  (L_ = 8192)
    const int j   = t & (L_ - 1);        // t % L_
    const int tid = threadIdx.x;         // 0..127

    float4 v;
    int row;
    if (j < K_) {
        row = __ldg(&keep_ids[b * K_ + j]);
        v = inputs[(size_t)(b * K_ + j) * VEC_PER_ROW + tid];
    } else {
        row = __ldg(&mask_ids[b * M_ + (j - K_)]);
        v = __ldg(&mask_emb[tid]);       // 2KB, L2/L1 resident after wave 1
    }

    out[((size_t)b * L_ + row) * VEC_PER_ROW + tid] = v;
}

extern "C" void kernel_launch(void* const* d_in, const int* in_sizes, int n_in,
                              void* d_out, int out_size)
{
    const float4* inputs   = (const float4*)d_in[0];
    const int*    mask_ids = (const int*)   d_in[1];
    const int*    keep_ids = (const int*)   d_in[2];
    const float4* mask_emb = (const float4*)d_in[3];
    float4*       out      = (float4*)      d_out;

    (void)in_sizes; (void)n_in; (void)out_size;

    // B*L = 65536 tasks, one CTA each, 128 threads = 128 float4 = one D-row.
    maskfiller_kernel<<<B_ * L_, 128>>>(inputs, mask_ids, keep_ids, mask_emb, out);
}

// round 9
// speedup vs baseline: 1.1741x; 1.1741x over previous
#include <cuda_runtime.h>
#include <cuda_bf16.h>

// MaskFiller: out[b, keep_ids[b,k], :] = inputs[b,k,:]
//             out[b, mask_ids[b,m], :] = mask_embedding[:]
// B=8, K=4096, M=4096, L=8192, D=512 (f32). Pure scatter-copy; HBM bound.
//
// R4: batch U=4 rows per CTA to raise per-thread MLP 1->4 (R3 was
// latency-bound: DRAM 47%, issue 22%, nothing saturated). Streaming cache
// hints keep indices+embedding L2-resident while inputs/output stream.
//
// Inputs (metadata order):
//   d_in[0] inputs            float32 [B, K, D]
//   d_in[1] mask_position_ids int32   [B, M]
//   d_in[2] keep_position_ids int32   [B, K]
//   d_in[3] mask_embedding    float32 [D]
//   d_in[4] axis              (unused; always -2)

#define B_ 8
#define K_ 4096
#define M_ 4096
#define L_ (K_ + M_)
#define D_ 512
#define VPR 128          // float4 per row (D/4)
#define U_  4            // rows per CTA

__global__ __launch_bounds__(128, 16)
void maskfiller_kernel(const float4* __restrict__ inputs,
                       const int*    __restrict__ mask_ids,
                       const int*    __restrict__ keep_ids,
                       const float4* __restrict__ mask_emb,
                       float4*       __restrict__ out)
{
    // CTA handles U_ consecutive tasks t0..t0+3. L_ and K_ are divisible by
    // U_, so all tasks in a CTA share the same batch b and the same branch.
    const int t0  = blockIdx.x * U_;
    const int b   = t0 >> 13;            // t0 / L_
    const int j0  = t0 & (L_ - 1);       // t0 % L_
    const int tid = threadIdx.x;         // 0..127, one float4 column

    float4* __restrict__ out_b = out + (size_t)b * L_ * VPR;

    if (j0 < K_) {
        // keep path: copy 4 input rows to scattered output rows
        int rows[U_];
        #pragma unroll
        for (int u = 0; u < U_; ++u)
            rows[u] = __ldg(&keep_ids[b * K_ + j0 + u]);

        float4 v[U_];
        const float4* __restrict__ src =
            inputs + ((size_t)b * K_ + j0) * VPR + tid;
        #pragma unroll
        for (int u = 0; u < U_; ++u)
            v[u] = __ldcs(src + u * VPR);          // 4 independent DRAM loads

        #pragma unroll
        for (int u = 0; u < U_; ++u)
            __stcs(&out_b[(size_t)rows[u] * VPR + tid], v[u]);
    } else {
        // mask path: broadcast embedding into 4 scattered output rows
        const float4 v = __ldg(&mask_emb[tid]);    // L2/L1 resident
        int rows[U_];
        #pragma unroll
        for (int u = 0; u < U_; ++u)
            rows[u] = __ldg(&mask_ids[b * M_ + (j0 - K_) + u]);

        #pragma unroll
        for (int u = 0; u < U_; ++u)
            __stcs(&out_b[(size_t)rows[u] * VPR + tid], v);
    }
}

extern "C" void kernel_launch(void* const* d_in, const int* in_sizes, int n_in,
                              void* d_out, int out_size)
{
    const float4* inputs   = (const float4*)d_in[0];
    const int*    mask_ids = (const int*)   d_in[1];
    const int*    keep_ids = (const int*)   d_in[2];
    const float4* mask_emb = (const float4*)d_in[3];
    float4*       out      = (float4*)      d_out;

    (void)in_sizes; (void)n_in; (void)out_size;

    // B*L / U_ = 16384 CTAs, 128 threads each, 4 rows per CTA.
    maskfiller_kernel<<<(B_ * L_) / U_, 128>>>(inputs, mask_ids, keep_ids,
                                               mask_emb, out);
}

// round 10
// speedup vs baseline: 1.1870x; 1.0110x over previous
#include <cuda_runtime.h>
#include <cuda_bf16.h>

// MaskFiller: out[b, keep_ids[b,k], :] = inputs[b,k,:]
//             out[b, mask_ids[b,m], :] = mask_embedding[:]
// B=8, K=4096, M=4096, L=8192, D=512 (f32). Pure scatter-copy; HBM bound.
//
// R9: U=4 -> U=8 rows per CTA. R4 measured DRAM 64.7%, issue 10.6%,
// occ 83.5% -> still latency-exposed, not issue/occupancy-bound. Deeper
// per-thread load batching (MLP 4->8) is the remaining lever per the
// 3-term LDG model (lat/MLP_eff term still dominant).
//
// Inputs (metadata order):
//   d_in[0] inputs            float32 [B, K, D]
//   d_in[1] mask_position_ids int32   [B, M]
//   d_in[2] keep_position_ids int32   [B, K]
//   d_in[3] mask_embedding    float32 [D]
//   d_in[4] axis              (unused; always -2)

#define B_ 8
#define K_ 4096
#define M_ 4096
#define L_ (K_ + M_)
#define D_ 512
#define VPR 128          // float4 per row (D/4)
#define U_  8            // rows per CTA

__global__ __launch_bounds__(128, 8)
void maskfiller_kernel(const float4* __restrict__ inputs,
                       const int*    __restrict__ mask_ids,
                       const int*    __restrict__ keep_ids,
                       const float4* __restrict__ mask_emb,
                       float4*       __restrict__ out)
{
    // CTA handles U_ consecutive tasks. K_ and L_ are divisible by U_, so
    // all tasks in a CTA share the same batch b and the same branch.
    const int t0  = blockIdx.x * U_;
    const int b   = t0 >> 13;            // t0 / L_
    const int j0  = t0 & (L_ - 1);       // t0 % L_
    const int tid = threadIdx.x;         // 0..127, one float4 column

    float4* __restrict__ out_b = out + (size_t)b * L_ * VPR;

    if (j0 < K_) {
        // keep path: copy U_ input rows to scattered output rows.
        // Front-batch all index loads, then all data loads (8-deep MLP),
        // then all stores.
        int rows[U_];
        #pragma unroll
        for (int u = 0; u < U_; ++u)
            rows[u] = __ldg(&keep_ids[b * K_ + j0 + u]);

        const float4* __restrict__ src =
            inputs + ((size_t)b * K_ + j0) * VPR + tid;
        float4 v[U_];
        #pragma unroll
        for (int u = 0; u < U_; ++u)
            v[u] = __ldcs(src + u * VPR);          // 8 independent DRAM loads

        #pragma unroll
        for (int u = 0; u < U_; ++u)
            __stcs(&out_b[(size_t)rows[u] * VPR + tid], v[u]);
    } else {
        // mask path: broadcast embedding into U_ scattered output rows.
        const float4 v = __ldg(&mask_emb[tid]);    // L2/L1 resident
        int rows[U_];
        #pragma unroll
        for (int u = 0; u < U_; ++u)
            rows[u] = __ldg(&mask_ids[b * M_ + (j0 - K_) + u]);

        #pragma unroll
        for (int u = 0; u < U_; ++u)
            __stcs(&out_b[(size_t)rows[u] * VPR + tid], v);
    }
}

extern "C" void kernel_launch(void* const* d_in, const int* in_sizes, int n_in,
                              void* d_out, int out_size)
{
    const float4* inputs   = (const float4*)d_in[0];
    const int*    mask_ids = (const int*)   d_in[1];
    const int*    keep_ids = (const int*)   d_in[2];
    const float4* mask_emb = (const float4*)d_in[3];
    float4*       out      = (float4*)      d_out;

    (void)in_sizes; (void)n_in; (void)out_size;

    // B*L / U_ = 8192 CTAs, 128 threads each, 8 rows per CTA.
    maskfiller_kernel<<<(B_ * L_) / U_, 128>>>(inputs, mask_ids, keep_ids,
                                               mask_emb, out);
}